// round 7
// baseline (speedup 1.0000x reference)
#include <cuda_runtime.h>
#include <cuda_fp16.h>
#include <math.h>
#include <stdint.h>

#define BB 8
#define TT 32
#define NN 1024
#define DIN 64
#define DR 128
#define DT_VAL 0.25f
#define KC 32
#define NCHUNK (NN / KC)
#define WSLOT (192 * 128)
#define AST 40      // A smem stride (halves)
#define BST 136     // B smem stride (halves)
#define WST 136     // epilogue W smem stride (halves)

// ---------------- device scratch ----------------
__device__ float  g_h  [BB * NN * DR];
__device__ float  g_hv1[BB * NN * DR];
__device__ float  g_z  [BB * NN * DR];
__device__ float  g_obs[BB * TT];
__device__ __half g_Ah [BB * NN * NN];          // half A (16.7 MB)
__device__ __half g_Wh [6 * WSLOT];             // half weights
__device__ __half g_Woh[DR * DIN];              // half Wo
__device__ __half g_Pa [BB * NN * 256];         // ping
__device__ __half g_Pb [BB * NN * 256];         // pong
__device__ __half g_hv1h[(size_t)BB * TT * NN * DR]; // half hv1 history

// ---------------- helpers ----------------
__device__ __forceinline__ void cpa16(void* s, const void* g) {
    uint32_t sa = (uint32_t)__cvta_generic_to_shared(s);
    asm volatile("cp.async.cg.shared.global [%0], [%1], 16;" :: "r"(sa), "l"(g));
}
__device__ __forceinline__ void ldsm4(uint32_t* r, uint32_t addr) {
    asm volatile("ldmatrix.sync.aligned.m8n8.x4.shared.b16 {%0,%1,%2,%3}, [%4];"
                 : "=r"(r[0]), "=r"(r[1]), "=r"(r[2]), "=r"(r[3]) : "r"(addr));
}
__device__ __forceinline__ void ldsm4t(uint32_t* r, uint32_t addr) {
    asm volatile("ldmatrix.sync.aligned.m8n8.x4.trans.shared.b16 {%0,%1,%2,%3}, [%4];"
                 : "=r"(r[0]), "=r"(r[1]), "=r"(r[2]), "=r"(r[3]) : "r"(addr));
}
#define MMA_F16(acc, a, b) \
    asm volatile( \
        "mma.sync.aligned.m16n8k16.row.col.f32.f16.f16.f32 " \
        "{%0,%1,%2,%3}, {%4,%5,%6,%7}, {%8,%9}, {%0,%1,%2,%3};" \
        : "+f"((acc)[0]), "+f"((acc)[1]), "+f"((acc)[2]), "+f"((acc)[3]) \
        : "r"((a)[0]), "r"((a)[1]), "r"((a)[2]), "r"((a)[3]), \
          "r"((b)[0]), "r"((b)[1]))

// ---------------- init h = broadcast(h0) ----------------
__global__ void init_h_kernel(const float* __restrict__ h0) {
    int idx = blockIdx.x * blockDim.x + threadIdx.x;
    const int total = BB * NN * DR;
    for (; idx < total; idx += gridDim.x * blockDim.x)
        g_h[idx] = h0[idx & (DR - 1)];
}

// ---------------- A -> half (vectorized) ----------------
__global__ void round_A_kernel(const float* __restrict__ A) {
    int idx = blockIdx.x * blockDim.x + threadIdx.x;
    const int total = BB * NN * NN / 4;
    for (; idx < total; idx += gridDim.x * blockDim.x) {
        float4 v = ((const float4*)A)[idx];
        union { uint2 u; __half2 h2[2]; } pk;
        pk.h2[0] = __floats2half2_rn(v.x, v.y);
        pk.h2[1] = __floats2half2_rn(v.z, v.w);
        *(uint2*)&g_Ah[idx * 4] = pk.u;
    }
}

// ---------------- weights -> half ----------------
__global__ void round_W_kernel(
    const float* __restrict__ W0, const float* __restrict__ W1,
    const float* __restrict__ Wout, const float* __restrict__ Wz,
    const float* __restrict__ Wr, const float* __restrict__ Wh,
    const float* __restrict__ Wo)
{
    const float* srcs[6] = {W0, W1, Wout, Wz, Wr, Wh};
    const int sizes[6] = {128*128, 128*128, 128*128, 192*128, 192*128, 192*128};
    for (int s = 0; s < 6; s++) {
        const float* src = srcs[s];
        __half* dst = g_Wh + s * WSLOT;
        for (int i = blockIdx.x * blockDim.x + threadIdx.x; i < sizes[s];
             i += gridDim.x * blockDim.x)
            dst[i] = __float2half(src[i]);
    }
    for (int i = blockIdx.x * blockDim.x + threadIdx.x; i < DR * DIN;
         i += gridDim.x * blockDim.x)
        g_Woh[i] = __float2half(Wo[i]);
}

// ---------------- obs[b,t] ----------------
__global__ void obs_kernel(const float* __restrict__ masks) {
    int bt = blockIdx.x;
    const float* m = masks + (size_t)bt * NN * DIN;
    float s = 0.f;
    for (int i = threadIdx.x; i < NN * DIN / 4; i += blockDim.x) {
        float4 v = ((const float4*)m)[i];
        s += fabsf(v.x) + fabsf(v.y) + fabsf(v.z) + fabsf(v.w);
    }
    __shared__ float red[256];
    red[threadIdx.x] = s;
    __syncthreads();
    for (int o = 128; o > 0; o >>= 1) {
        if (threadIdx.x < o) red[threadIdx.x] += red[threadIdx.x + o];
        __syncthreads();
    }
    if (threadIdx.x == 0) g_obs[bt] = (red[0] > 1e-4f) ? 1.f : 0.f;
}

// ---------------- initial projection: P = half(h @ W0) --------------------
__global__ __launch_bounds__(256) void proj_h0(
    const float* __restrict__ h, const __half* __restrict__ W,
    __half* __restrict__ P)
{
    __shared__ __half Xs[64 * AST];
    __shared__ __half Ws[KC * BST];

    const int rowTile = blockIdx.x * 64;
    const int b  = rowTile >> 10;
    const int i0 = rowTile & (NN - 1);

    const int tid  = threadIdx.x;
    const int lane = tid & 31, warp = tid >> 5;
    const int wm = warp & 1, wn = warp >> 1;
    const int g  = lane >> 2, tig = lane & 3;
    const int quad = lane >> 3;
    const int lrow = (quad & 1) * 8 + (lane & 7);
    const int lcol = (quad >> 1) * 8;

    const float* hb = h + ((size_t)b * NN + i0) * DR;
    const uint32_t sXs = (uint32_t)__cvta_generic_to_shared(Xs);
    const uint32_t sWs = (uint32_t)__cvta_generic_to_shared(Ws);

    float acc[2][4][4] = {};

    for (int k0 = 0; k0 < DR; k0 += KC) {
        {
            int r = tid >> 2, kq = tid & 3;
            float4 v0 = *(const float4*)(hb + (size_t)r * DR + k0 + kq * 8);
            float4 v1 = *(const float4*)(hb + (size_t)r * DR + k0 + kq * 8 + 4);
            union { uint4 u; __half2 h2[4]; } pk;
            pk.h2[0] = __floats2half2_rn(v0.x, v0.y);
            pk.h2[1] = __floats2half2_rn(v0.z, v0.w);
            pk.h2[2] = __floats2half2_rn(v1.x, v1.y);
            pk.h2[3] = __floats2half2_rn(v1.z, v1.w);
            *(uint4*)&Xs[r * AST + kq * 8] = pk.u;
        }
        #pragma unroll
        for (int l = 0; l < 2; l++) {
            int idx = tid + l * 256;
            int kk2 = idx >> 4, cq = idx & 15;
            *(uint4*)&Ws[kk2 * BST + cq * 8] =
                *(const uint4*)(W + (size_t)(k0 + kk2) * 128 + cq * 8);
        }
        __syncthreads();
        #pragma unroll
        for (int ks = 0; ks < 2; ks++) {
            const int kk = ks * 16;
            uint32_t a[2][4], bq[2][4];
            #pragma unroll
            for (int mf = 0; mf < 2; mf++)
                ldsm4(a[mf], sXs + ((wm*32 + mf*16 + lrow) * AST + kk + lcol) * 2);
            #pragma unroll
            for (int p = 0; p < 2; p++)
                ldsm4t(bq[p], sWs + ((kk + lrow) * BST + wn*32 + p*16 + lcol) * 2);
            #pragma unroll
            for (int mf = 0; mf < 2; mf++) {
                MMA_F16(acc[mf][0], a[mf], &bq[0][0]);
                MMA_F16(acc[mf][1], a[mf], &bq[0][2]);
                MMA_F16(acc[mf][2], a[mf], &bq[1][0]);
                MMA_F16(acc[mf][3], a[mf], &bq[1][2]);
            }
        }
        __syncthreads();
    }
    __half* Pbp = P + ((size_t)b * NN + i0) * 128;
    #pragma unroll
    for (int mf = 0; mf < 2; mf++)
        #pragma unroll
        for (int hf = 0; hf < 2; hf++) {
            int row = wm*32 + mf*16 + g + hf*8;
            #pragma unroll
            for (int nf = 0; nf < 4; nf++) {
                int col = wn*32 + nf*8 + 2*tig;
                *(__half2*)(Pbp + (size_t)row * 128 + col) =
                    __floats2half2_rn(acc[mf][nf][hf*2 + 0], acc[mf][nf][hf*2 + 1]);
            }
        }
}

// ---------------- epilogue GEMM: Pout64x128 = Ts(64xK2) @ Wsm(K2x128) -----
template<int K2, int TST_>
__device__ __forceinline__ void egemm(
    uint32_t sTs, uint32_t sW, __half* __restrict__ PoutB, int ldPout,
    int wm, int wn, int lrow, int lcol, int g, int tig)
{
    float acc2[2][4][4] = {};
    #pragma unroll
    for (int ks = 0; ks < K2 / 16; ks++) {
        const int kk = ks * 16;
        uint32_t a[2][4], bq[2][4];
        #pragma unroll
        for (int mf = 0; mf < 2; mf++)
            ldsm4(a[mf], sTs + ((wm*32 + mf*16 + lrow) * TST_ + kk + lcol) * 2);
        #pragma unroll
        for (int p = 0; p < 2; p++)
            ldsm4t(bq[p], sW + ((kk + lrow) * WST + wn*32 + p*16 + lcol) * 2);
        #pragma unroll
        for (int mf = 0; mf < 2; mf++) {
            MMA_F16(acc2[mf][0], a[mf], &bq[0][0]);
            MMA_F16(acc2[mf][1], a[mf], &bq[0][2]);
            MMA_F16(acc2[mf][2], a[mf], &bq[1][0]);
            MMA_F16(acc2[mf][3], a[mf], &bq[1][2]);
        }
    }
    #pragma unroll
    for (int mf = 0; mf < 2; mf++)
        #pragma unroll
        for (int hf = 0; hf < 2; hf++) {
            int row = wm*32 + mf*16 + g + hf*8;
            #pragma unroll
            for (int nf = 0; nf < 4; nf++) {
                int col = wn*32 + nf*8 + 2*tig;
                *(__half2*)(PoutB + (size_t)row * ldPout + col) =
                    __floats2half2_rn(acc2[mf][nf][hf*2 + 0], acc2[mf][nf][hf*2 + 1]);
            }
        }
}

// ---------------- fused A-mult + epilogue projection ----------------------
// Main: G = A @ Bop[:, colOff:colOff+128] (half, 64x128 tile, cp.async dbl buf)
// EP 0: u=tanh(G+ba);                     Pout = u@Wp0           (K2=128)
// EP 1: h=hin+(G+ba)dt -> dst;            Pout = h@Wp0           (K2=128) [initial]
// EP 2: hv1=hin+(G+ba)dt -> dst,hist;     Pout = [xm|hv1]@{Wp0,Wp1} (K2=192, ld 256)
// EP 3: cb0: z=sig(G+ba) -> dst.  cb1: r=sig(G+bb);
//                                         Pout = [xm|r*hv1]@Wp0  (K2=192)
// EP 4: h=hin+obs*z*(tanh(G+ba)-hin) -> dst; Pout = h@Wp0        (K2=128)
template<int EP>
__global__ __launch_bounds__(256) void fused_h(
    const __half* __restrict__ A, const __half* __restrict__ Bop, int ldB,
    const float* __restrict__ ba, const float* __restrict__ bb,
    const __half* __restrict__ Wp0, const __half* __restrict__ Wp1,
    __half* __restrict__ Pout, int ldPout,
    float* __restrict__ dst, const float* __restrict__ hin,
    const float* __restrict__ zsr, const float* __restrict__ obsArr, int tIdx,
    const float* __restrict__ xv, const float* __restrict__ xmk,
    __half* __restrict__ histPtr)
{
    constexpr int K2   = (EP == 2 || EP == 3) ? 192 : 128;
    constexpr int TST_ = (K2 == 192) ? 200 : 136;
    constexpr int NW   = (EP == 2) ? 2 : 1;

    extern __shared__ __half smh[];
    __half* As  = smh;                       // 2*64*AST
    __half* Bs  = smh + 2 * 64 * AST;        // 2*KC*BST
    __half* Wsm = Bs + 2 * KC * BST;         // NW*K2*WST
    __half* Ts  = smh;                       // alias main region (post-loop)

    const int b = blockIdx.z;
    const int rowTile = blockIdx.x * 64;
    const int cb = blockIdx.y;
    const int colOff = cb * 128;
    const float* bias = (EP == 3 && cb == 1) ? bb : ba;

    const int tid  = threadIdx.x;
    const int lane = tid & 31, warp = tid >> 5;
    const int wm = warp & 1, wn = warp >> 1;
    const int g  = lane >> 2, tig = lane & 3;
    const int quad = lane >> 3;
    const int lrow = (quad & 1) * 8 + (lane & 7);
    const int lcol = (quad >> 1) * 8;

    const __half* Ab = A + (size_t)b * NN * NN + (size_t)rowTile * NN;
    const __half* Pb = Bop + (size_t)b * NN * ldB + colOff;

    const uint32_t sAs = (uint32_t)__cvta_generic_to_shared(As);
    const uint32_t sBs = (uint32_t)__cvta_generic_to_shared(Bs);
    const uint32_t sW  = (uint32_t)__cvta_generic_to_shared(Wsm);
    const uint32_t sTs = (uint32_t)__cvta_generic_to_shared(Ts);

    const bool doEpi = (EP != 3) || (cb == 1);

    float acc[2][4][4] = {};

    auto prefetch = [&](int chunk, int buf) {
        __half* Ad = As + buf * 64 * AST;
        __half* Bd = Bs + buf * KC * BST;
        {
            int r = tid >> 2, kq = tid & 3;
            cpa16(Ad + r * AST + kq * 8, Ab + (size_t)r * NN + chunk * KC + kq * 8);
        }
        #pragma unroll
        for (int l = 0; l < 2; l++) {
            int idx = tid + l * 256;
            int kk2 = idx >> 4, cq = idx & 15;
            cpa16(Bd + kk2 * BST + cq * 8,
                  Pb + (size_t)(chunk * KC + kk2) * ldB + cq * 8);
        }
        asm volatile("cp.async.commit_group;");
    };

    // epilogue W load rides in the first commit group (overlaps whole main loop)
    if (doEpi) {
        #pragma unroll
        for (int w = 0; w < NW; w++) {
            const __half* Wg = w ? Wp1 : Wp0;
            __half* Wd = Wsm + w * K2 * WST;
            for (int i = tid; i < K2 * 16; i += 256) {
                int r = i >> 4, cq = i & 15;
                cpa16(Wd + r * WST + cq * 8, Wg + (size_t)r * 128 + cq * 8);
            }
        }
    }
    prefetch(0, 0);

    for (int ch = 0; ch < NCHUNK; ch++) {
        int buf = ch & 1;
        if (ch + 1 < NCHUNK) {
            prefetch(ch + 1, buf ^ 1);
            asm volatile("cp.async.wait_group 1;");
        } else {
            asm volatile("cp.async.wait_group 0;");
        }
        __syncthreads();
        const uint32_t aBase = sAs + buf * 64 * AST * 2;
        const uint32_t bBase = sBs + buf * KC * BST * 2;
        #pragma unroll
        for (int ks = 0; ks < 2; ks++) {
            const int kk = ks * 16;
            uint32_t a[2][4], bq[2][4];
            #pragma unroll
            for (int mf = 0; mf < 2; mf++)
                ldsm4(a[mf], aBase + ((wm*32 + mf*16 + lrow) * AST + kk + lcol) * 2);
            #pragma unroll
            for (int p = 0; p < 2; p++)
                ldsm4t(bq[p], bBase + ((kk + lrow) * BST + wn*32 + p*16 + lcol) * 2);
            #pragma unroll
            for (int mf = 0; mf < 2; mf++) {
                MMA_F16(acc[mf][0], a[mf], &bq[0][0]);
                MMA_F16(acc[mf][1], a[mf], &bq[0][2]);
                MMA_F16(acc[mf][2], a[mf], &bq[1][0]);
                MMA_F16(acc[mf][3], a[mf], &bq[1][2]);
            }
        }
        __syncthreads();
    }

    // ---- activation epilogue: fp32 outputs + Ts staging (aliases main smem)
    const float ob = (EP == 4) ? obsArr[b * TT + tIdx] : 0.f;
    #pragma unroll
    for (int mf = 0; mf < 2; mf++)
        #pragma unroll
        for (int hf = 0; hf < 2; hf++) {
            int row = wm*32 + mf*16 + g + hf*8;
            int grow = rowTile + row;
            size_t idx = ((size_t)b * NN + grow) * DR;
            #pragma unroll
            for (int nf = 0; nf < 4; nf++) {
                int col = wn*32 + nf*8 + 2*tig;
                float s0 = acc[mf][nf][hf*2 + 0] + bias[col];
                float s1 = acc[mf][nf][hf*2 + 1] + bias[col + 1];
                if (EP == 0) {
                    *(__half2*)&Ts[row * TST_ + col] =
                        __floats2half2_rn(tanhf(s0), tanhf(s1));
                } else if (EP == 1) {
                    float v0 = hin[idx + col]     + s0 * DT_VAL;
                    float v1 = hin[idx + col + 1] + s1 * DT_VAL;
                    *(float2*)(dst + idx + col) = make_float2(v0, v1);
                    *(__half2*)&Ts[row * TST_ + col] = __floats2half2_rn(v0, v1);
                } else if (EP == 2) {
                    float v0 = hin[idx + col]     + s0 * DT_VAL;
                    float v1 = hin[idx + col + 1] + s1 * DT_VAL;
                    *(float2*)(dst + idx + col) = make_float2(v0, v1);
                    __half2 hv = __floats2half2_rn(v0, v1);
                    *(__half2*)&Ts[row * TST_ + 64 + col] = hv;
                    size_t hidx = (((size_t)b * TT + tIdx) * NN + grow) * DR + col;
                    *(__half2*)(histPtr + hidx) = hv;
                } else if (EP == 3) {
                    float v0 = 1.f / (1.f + __expf(-s0));
                    float v1 = 1.f / (1.f + __expf(-s1));
                    if (cb == 0) {
                        *(float2*)(dst + idx + col) = make_float2(v0, v1);
                    } else {
                        // r * hv1
                        float rh0 = v0 * hin[idx + col];
                        float rh1 = v1 * hin[idx + col + 1];
                        *(__half2*)&Ts[row * TST_ + 64 + col] =
                            __floats2half2_rn(rh0, rh1);
                    }
                } else { // EP 4
                    float c0 = tanhf(s0), c1 = tanhf(s1);
                    float h0v = hin[idx + col], h1v = hin[idx + col + 1];
                    float v0 = h0v + ob * zsr[idx + col]     * (c0 - h0v);
                    float v1 = h1v + ob * zsr[idx + col + 1] * (c1 - h1v);
                    *(float2*)(dst + idx + col) = make_float2(v0, v1);
                    *(__half2*)&Ts[row * TST_ + col] = __floats2half2_rn(v0, v1);
                }
            }
        }

    if (EP == 3 && cb == 0) return;   // whole CTA: z written, no projection

    // xm tile -> Ts[:, 0:64] for concat inputs
    if (EP == 2 || EP == 3) {
        const float* xvb = xv + (((size_t)b * TT + tIdx) * NN + rowTile) * DIN;
        const float* xmb = xmk + (((size_t)b * TT + tIdx) * NN + rowTile) * DIN;
        for (int i = tid; i < 512; i += 256) {
            int r = i >> 3, cq = i & 7;
            float4 v0 = *(const float4*)(xvb + (size_t)r * DIN + cq * 8);
            float4 v1 = *(const float4*)(xvb + (size_t)r * DIN + cq * 8 + 4);
            float4 m0 = *(const float4*)(xmb + (size_t)r * DIN + cq * 8);
            float4 m1 = *(const float4*)(xmb + (size_t)r * DIN + cq * 8 + 4);
            union { uint4 u; __half2 h2[4]; } pk;
            pk.h2[0] = __floats2half2_rn(v0.x * m0.x, v0.y * m0.y);
            pk.h2[1] = __floats2half2_rn(v0.z * m0.z, v0.w * m0.w);
            pk.h2[2] = __floats2half2_rn(v1.x * m1.x, v1.y * m1.y);
            pk.h2[3] = __floats2half2_rn(v1.z * m1.z, v1.w * m1.w);
            *(uint4*)&Ts[r * TST_ + cq * 8] = pk.u;
        }
    }
    __syncthreads();

    __half* PoutB = Pout + ((size_t)b * NN + rowTile) * ldPout;
    egemm<K2, TST_>(sTs, sW, PoutB, ldPout, wm, wn, lrow, lcol, g, tig);
    if (EP == 2)
        egemm<K2, TST_>(sTs, sW + K2 * WST * 2, PoutB + 128, ldPout,
                        wm, wn, lrow, lcol, g, tig);
}

// ---------------- batched output head ----------------
__global__ __launch_bounds__(128) void outgemm_h(
    const __half* __restrict__ hv1h, const __half* __restrict__ Wo,
    const float* __restrict__ bo, float* __restrict__ out)
{
    __shared__ __half As[64 * BST];
    __shared__ __half Ws[DR * 72];

    const int n0 = blockIdx.x * 64;
    const int t  = blockIdx.y + 1;
    const int b  = blockIdx.z;

    const int tid  = threadIdx.x;
    const int lane = tid & 31, warp = tid >> 5;
    const int wm = warp & 1, wn = warp >> 1;
    const int g  = lane >> 2, tig = lane & 3;
    const int quad = lane >> 3;
    const int lrow = (quad & 1) * 8 + (lane & 7);
    const int lcol = (quad >> 1) * 8;

    const __half* Hb = hv1h + (((size_t)b * TT + t) * NN + n0) * DR;

    for (int i = tid; i < 64 * 16; i += 128) {
        int r = i >> 4, cq = i & 15;
        *(uint4*)&As[r * BST + cq * 8] = *(const uint4*)(Hb + (size_t)r * DR + cq * 8);
    }
    for (int i = tid; i < DR * 8; i += 128) {
        int r = i >> 3, cq = i & 7;
        *(uint4*)&Ws[r * 72 + cq * 8] = *(const uint4*)(Wo + (size_t)r * DIN + cq * 8);
    }
    __syncthreads();

    const uint32_t sAs = (uint32_t)__cvta_generic_to_shared(As);
    const uint32_t sWs = (uint32_t)__cvta_generic_to_shared(Ws);

    float acc[2][4][4] = {};
    #pragma unroll
    for (int ks = 0; ks < 8; ks++) {
        const int kk = ks * 16;
        uint32_t a[2][4], bq[2][4];
        #pragma unroll
        for (int mf = 0; mf < 2; mf++)
            ldsm4(a[mf], sAs + ((wm*32 + mf*16 + lrow) * BST + kk + lcol) * 2);
        #pragma unroll
        for (int p = 0; p < 2; p++)
            ldsm4t(bq[p], sWs + ((kk + lrow) * 72 + wn*32 + p*16 + lcol) * 2);
        #pragma unroll
        for (int mf = 0; mf < 2; mf++) {
            MMA_F16(acc[mf][0], a[mf], &bq[0][0]);
            MMA_F16(acc[mf][1], a[mf], &bq[0][2]);
            MMA_F16(acc[mf][2], a[mf], &bq[1][0]);
            MMA_F16(acc[mf][3], a[mf], &bq[1][2]);
        }
    }

    float* obp = out + (((size_t)b * (TT - 1) + (t - 1)) * NN + n0) * DIN;
    #pragma unroll
    for (int mf = 0; mf < 2; mf++)
        #pragma unroll
        for (int hf = 0; hf < 2; hf++) {
            int row = wm*32 + mf*16 + g + hf*8;
            #pragma unroll
            for (int nf = 0; nf < 4; nf++) {
                int col = wn*32 + nf*8 + 2*tig;
                float v0 = acc[mf][nf][hf*2 + 0] + bo[col];
                float v1 = acc[mf][nf][hf*2 + 1] + bo[col + 1];
                *(float2*)(obp + (size_t)row * DIN + col) = make_float2(v0, v1);
            }
        }
}

// ---------------- driver ----------------
#define SM_MAIN ((2 * 64 * AST + 2 * KC * BST) * 2)
#define SM_EP01 (SM_MAIN + 128 * WST * 2)
#define SM_EP2  (SM_MAIN + 2 * 192 * WST * 2)
#define SM_EP3  (SM_MAIN + 192 * WST * 2)
#define SM_EP4  SM_EP01

extern "C" void kernel_launch(void* const* d_in, const int* in_sizes, int n_in,
                              void* d_out, int out_size)
{
    const float* values = (const float*)d_in[0];
    const float* masks  = (const float*)d_in[1];
    const float* A      = (const float*)d_in[2];
    const float* h0     = (const float*)d_in[3];
    const float* W0   = (const float*)d_in[4];
    const float* b0   = (const float*)d_in[5];
    const float* W1   = (const float*)d_in[6];
    const float* b1   = (const float*)d_in[7];
    const float* Wout = (const float*)d_in[8];
    const float* bout = (const float*)d_in[9];
    const float* Wz   = (const float*)d_in[10];
    const float* bz   = (const float*)d_in[11];
    const float* Wr   = (const float*)d_in[12];
    const float* br   = (const float*)d_in[13];
    const float* Wh   = (const float*)d_in[14];
    const float* bh   = (const float*)d_in[15];
    const float* Wo   = (const float*)d_in[16];
    const float* bo   = (const float*)d_in[17];
    float* out = (float*)d_out;

    float *h, *hv1, *z, *obs;
    __half *Ah, *Wh6, *Woh, *Pa, *Pb, *hv1h;
    cudaGetSymbolAddress((void**)&h,    g_h);
    cudaGetSymbolAddress((void**)&hv1,  g_hv1);
    cudaGetSymbolAddress((void**)&z,    g_z);
    cudaGetSymbolAddress((void**)&obs,  g_obs);
    cudaGetSymbolAddress((void**)&Ah,   g_Ah);
    cudaGetSymbolAddress((void**)&Wh6,  g_Wh);
    cudaGetSymbolAddress((void**)&Woh,  g_Woh);
    cudaGetSymbolAddress((void**)&Pa,   g_Pa);
    cudaGetSymbolAddress((void**)&Pb,   g_Pb);
    cudaGetSymbolAddress((void**)&hv1h, g_hv1h);

    cudaFuncSetAttribute(fused_h<0>, cudaFuncAttributeMaxDynamicSharedMemorySize, SM_EP01);
    cudaFuncSetAttribute(fused_h<1>, cudaFuncAttributeMaxDynamicSharedMemorySize, SM_EP01);
    cudaFuncSetAttribute(fused_h<2>, cudaFuncAttributeMaxDynamicSharedMemorySize, SM_EP2);
    cudaFuncSetAttribute(fused_h<3>, cudaFuncAttributeMaxDynamicSharedMemorySize, SM_EP3);
    cudaFuncSetAttribute(fused_h<4>, cudaFuncAttributeMaxDynamicSharedMemorySize, SM_EP4);

    init_h_kernel<<<256, 256>>>(h0);
    round_A_kernel<<<512, 256>>>(A);
    round_W_kernel<<<128, 256>>>(W0, W1, Wout, Wz, Wr, Wh, Wo);
    obs_kernel<<<BB * TT, 256>>>(masks);

    const __half* tW1   = Wh6 + 1 * WSLOT;
    const __half* tWout = Wh6 + 2 * WSLOT;
    const __half* tWz   = Wh6 + 3 * WSLOT;
    const __half* tWr   = Wh6 + 4 * WSLOT;
    const __half* tWh   = Wh6 + 5 * WSLOT;
    const __half* tW0   = Wh6 + 0 * WSLOT;

    dim3 fg(16, 1, 8), fg2(16, 2, 8);
    __half* cur = Pa;
    __half* nxt = Pb;
    auto swap = [&]() { __half* t2 = cur; cur = nxt; nxt = t2; };

    // P0 = h @ W0
    proj_h0<<<128, 256>>>(h, tW0, cur);

    // initial ODE-only step: h <- h + ode(h)*dt ; epilogue P = h@W0
    fused_h<0><<<fg, 256, SM_EP01>>>(Ah, cur, 128, b0, nullptr, tW1, nullptr,
        nxt, 128, nullptr, nullptr, nullptr, nullptr, 0, nullptr, nullptr, nullptr);
    swap();
    fused_h<0><<<fg, 256, SM_EP01>>>(Ah, cur, 128, b1, nullptr, tWout, nullptr,
        nxt, 128, nullptr, nullptr, nullptr, nullptr, 0, nullptr, nullptr, nullptr);
    swap();
    fused_h<1><<<fg, 256, SM_EP01>>>(Ah, cur, 128, bout, nullptr, tW0, nullptr,
        nxt, 128, h, h, nullptr, nullptr, 0, nullptr, nullptr, nullptr);
    swap();

    for (int t = 0; t < TT; t++) {
        // K1: u1 = tanh(A@P + b0); P = u1@W1
        fused_h<0><<<fg, 256, SM_EP01>>>(Ah, cur, 128, b0, nullptr, tW1, nullptr,
            nxt, 128, nullptr, nullptr, nullptr, nullptr, 0, nullptr, nullptr, nullptr);
        swap();
        // K2: u2 = tanh(A@P + b1); P = u2@Wout
        fused_h<0><<<fg, 256, SM_EP01>>>(Ah, cur, 128, b1, nullptr, tWout, nullptr,
            nxt, 128, nullptr, nullptr, nullptr, nullptr, 0, nullptr, nullptr, nullptr);
        swap();
        // K3: hv1 = h + (A@P + bout)*dt; hist; P256 = [xm|hv1]@{Wz,Wr}
        fused_h<2><<<fg, 256, SM_EP2>>>(Ah, cur, 128, bout, nullptr, tWz, tWr,
            nxt, 256, hv1, h, nullptr, nullptr, t, values, masks, hv1h);
        swap();
        // K4: cb0 z = sig(A@P[:,:128]+bz); cb1 r = sig(..+br), P = [xm|r*hv1]@Wh
        fused_h<3><<<fg2, 256, SM_EP3>>>(Ah, cur, 256, bz, br, tWh, nullptr,
            nxt, 128, z, hv1, nullptr, nullptr, t, values, masks, nullptr);
        swap();
        // K5: h = hv1 + obs*z*(tanh(A@P+bh)-hv1); P = h@W0
        fused_h<4><<<fg, 256, SM_EP4>>>(Ah, cur, 128, bh, nullptr, tW0, nullptr,
            nxt, 128, h, hv1, z, obs, t, nullptr, nullptr, nullptr);
        swap();
    }

    dim3 og(NN / 64, TT - 1, BB);
    outgemm_h<<<og, 128>>>(hv1h, Woh, bo, out);
}